// round 2
// baseline (speedup 1.0000x reference)
#include <cuda_runtime.h>

#define NMAX 131072
#define FD 16

__device__ float g_hA[NMAX * FD];
__device__ float g_xnA[NMAX * FD];
__device__ float g_hB[NMAX * FD];
__device__ float g_xnB[NMAX * FD];
__device__ float g_acc[NMAX * FD];
__device__ float g_den[NMAX];
__device__ __align__(16) float g_v[20];
__device__ int g_idx64;

__device__ __forceinline__ float d4(float4 a, float4 b) {
    return a.x * b.x + a.y * b.y + a.z * b.z + a.w * b.w;
}

// ---------------------------------------------------------------------------
// Detect whether the index arrays are int64 (high 32-bit words all zero at odd
// int32 positions) or int32. Node ids < 2^31 and nonnegative, so for int64
// data every odd 32-bit word is 0; for int32 data they are random node ids.
// ---------------------------------------------------------------------------
__global__ void detect_kernel(const unsigned int* __restrict__ a) {
    __shared__ int any;
    if (threadIdx.x == 0) any = 0;
    __syncthreads();
    unsigned int v = a[2 * threadIdx.x + 1] | a[2 * (threadIdx.x + 256) + 1];
    if (v) atomicOr(&any, 1);
    __syncthreads();
    if (threadIdx.x == 0) g_idx64 = (any == 0) ? 1 : 0;
}

// ---------------------------------------------------------------------------
// v[k] = sum_j gather_w[j] * lin2_w[j,k];  g_v[16] = gather_w . lin2_b
// ---------------------------------------------------------------------------
__global__ void calc_v_kernel(const float* __restrict__ lin2_w,
                              const float* __restrict__ lin2_b,
                              const float* __restrict__ gather_w) {
    int t = threadIdx.x;
    if (t < 16) {
        float s = 0.f;
        #pragma unroll
        for (int j = 0; j < 64; j++) s += gather_w[j] * lin2_w[j * 16 + t];
        g_v[t] = s;
    } else if (t == 16) {
        float s = 0.f;
        #pragma unroll
        for (int j = 0; j < 64; j++) s += gather_w[j] * lin2_b[j];
        g_v[16] = s;
    }
}

__global__ void init_y_kernel(float* __restrict__ y,
                              const float* __restrict__ gather_b, int g) {
    int i = blockIdx.x * blockDim.x + threadIdx.x;
    if (i < g) y[i] = gather_b[0];
}

// ---------------------------------------------------------------------------
// h = relu(x @ W1^T + b1), xn = h / max(||h||, 1e-12); also zero acc/den.
// Block of 128 threads stages 128 rows of x (75 floats each) in smem.
// ---------------------------------------------------------------------------
__global__ void lin1_kernel(const float* __restrict__ x,
                            const float* __restrict__ w,
                            const float* __restrict__ b, int n) {
    __shared__ float sx[128 * 75];
    __shared__ float sw[75 * 16];
    __shared__ float sb[16];
    int tid = threadIdx.x;
    int bstart = blockIdx.x * 128;

    for (int i = tid; i < 75 * 16; i += 128) {
        int j = i / 75, k = i % 75;       // w is [16,75] row-major
        sw[k * 16 + j] = w[i];
    }
    if (tid < 16) sb[tid] = b[tid];

    int nodes = min(128, n - bstart);
    if (nodes == 128) {
        const float4* src = (const float4*)(x + (size_t)bstart * 75);
        float4* dst = (float4*)sx;
        #pragma unroll 4
        for (int i = tid; i < 128 * 75 / 4; i += 128) dst[i] = src[i];
    } else {
        for (int i = tid; i < nodes * 75; i += 128)
            sx[i] = x[(size_t)bstart * 75 + i];
    }
    __syncthreads();
    if (tid >= nodes) return;
    int node = bstart + tid;

    float4 a0 = make_float4(sb[0], sb[1], sb[2], sb[3]);
    float4 a1 = make_float4(sb[4], sb[5], sb[6], sb[7]);
    float4 a2 = make_float4(sb[8], sb[9], sb[10], sb[11]);
    float4 a3 = make_float4(sb[12], sb[13], sb[14], sb[15]);

    const float* row = sx + tid * 75;
    const float4* swv = (const float4*)sw;
    #pragma unroll 5
    for (int k = 0; k < 75; k++) {
        float rk = row[k];
        float4 w0 = swv[k * 4 + 0];
        float4 w1 = swv[k * 4 + 1];
        float4 w2 = swv[k * 4 + 2];
        float4 w3 = swv[k * 4 + 3];
        a0.x += rk * w0.x; a0.y += rk * w0.y; a0.z += rk * w0.z; a0.w += rk * w0.w;
        a1.x += rk * w1.x; a1.y += rk * w1.y; a1.z += rk * w1.z; a1.w += rk * w1.w;
        a2.x += rk * w2.x; a2.y += rk * w2.y; a2.z += rk * w2.z; a2.w += rk * w2.w;
        a3.x += rk * w3.x; a3.y += rk * w3.y; a3.z += rk * w3.z; a3.w += rk * w3.w;
    }
    a0.x = fmaxf(a0.x, 0.f); a0.y = fmaxf(a0.y, 0.f); a0.z = fmaxf(a0.z, 0.f); a0.w = fmaxf(a0.w, 0.f);
    a1.x = fmaxf(a1.x, 0.f); a1.y = fmaxf(a1.y, 0.f); a1.z = fmaxf(a1.z, 0.f); a1.w = fmaxf(a1.w, 0.f);
    a2.x = fmaxf(a2.x, 0.f); a2.y = fmaxf(a2.y, 0.f); a2.z = fmaxf(a2.z, 0.f); a2.w = fmaxf(a2.w, 0.f);
    a3.x = fmaxf(a3.x, 0.f); a3.y = fmaxf(a3.y, 0.f); a3.z = fmaxf(a3.z, 0.f); a3.w = fmaxf(a3.w, 0.f);

    float ss = d4(a0, a0) + d4(a1, a1) + d4(a2, a2) + d4(a3, a3);
    float inv = 1.f / fmaxf(sqrtf(ss), 1e-12f);

    size_t o = (size_t)node * 4;
    float4* hv = (float4*)g_hA + o;
    hv[0] = a0; hv[1] = a1; hv[2] = a2; hv[3] = a3;
    float4* xv = (float4*)g_xnA + o;
    xv[0] = make_float4(a0.x * inv, a0.y * inv, a0.z * inv, a0.w * inv);
    xv[1] = make_float4(a1.x * inv, a1.y * inv, a1.z * inv, a1.w * inv);
    xv[2] = make_float4(a2.x * inv, a2.y * inv, a2.z * inv, a2.w * inv);
    xv[3] = make_float4(a3.x * inv, a3.y * inv, a3.z * inv, a3.w * inv);
    float4 z = make_float4(0.f, 0.f, 0.f, 0.f);
    float4* av = (float4*)g_acc + o;
    av[0] = z; av[1] = z; av[2] = z; av[3] = z;
    g_den[node] = 0.f;
}

// ---------------------------------------------------------------------------
// One fused edge pass: acc[dst] += exp(beta * xn_s.xn_d) * h[src];
//                      den[dst] += exp(...). 4 lanes cooperate per edge.
// ---------------------------------------------------------------------------
__global__ void edge_kernel(const void* __restrict__ eiv, long long E,
                            const float* __restrict__ beta, int which) {
    const float* xn = which ? g_xnB : g_xnA;
    const float* h  = which ? g_hB  : g_hA;
    const float b0 = __ldg(beta);
    int lane = threadIdx.x & 31;
    int c = lane & 3;
    long long warp = (((long long)blockIdx.x * blockDim.x) + threadIdx.x) >> 5;
    long long ebase = warp * 8;
    if (ebase >= E) return;
    long long e = ebase + (lane >> 2);
    bool ok = (e < E);
    int s = 0, d = 0;
    if (ok) {
        if (g_idx64) {
            const long long* ei = (const long long*)eiv;
            s = (int)__ldg(ei + e);
            d = (int)__ldg(ei + E + e);
        } else {
            const int* ei = (const int*)eiv;
            s = __ldg(ei + e);
            d = __ldg(ei + E + e);
        }
    }
    float p = 0.f;
    float4 xs, xd;
    if (ok) {
        const float4* xnv = (const float4*)xn;
        xs = __ldg(xnv + s * 4 + c);
        xd = __ldg(xnv + d * 4 + c);
        p = d4(xs, xd);
    }
    p += __shfl_xor_sync(0xffffffffu, p, 1);
    p += __shfl_xor_sync(0xffffffffu, p, 2);
    if (!ok) return;
    float ex = __expf(b0 * p);
    float4 hs = __ldg((const float4*)h + s * 4 + c);
    float* ap = g_acc + ((size_t)d * 16) + c * 4;
    asm volatile("red.global.add.v4.f32 [%0], {%1,%2,%3,%4};"
                 :: "l"(ap), "f"(ex * hs.x), "f"(ex * hs.y),
                    "f"(ex * hs.z), "f"(ex * hs.w)
                 : "memory");
    if (c == 0) atomicAdd(g_den + d, ex);
}

// ---------------------------------------------------------------------------
// Add self-loop analytically, divide by denom, renormalize into buffer B,
// re-zero acc/den for the second pass.
// ---------------------------------------------------------------------------
__global__ void finalize_kernel(const float* __restrict__ beta, int n) {
    int i = blockIdx.x * blockDim.x + threadIdx.x;
    if (i >= n) return;
    size_t o = (size_t)i * 4;
    const float4* hv = (const float4*)g_hA + o;
    const float4* xv = (const float4*)g_xnA + o;
    float4* av = (float4*)g_acc + o;
    float4 h0 = hv[0], h1 = hv[1], h2 = hv[2], h3 = hv[3];
    float4 x0 = xv[0], x1 = xv[1], x2 = xv[2], x3 = xv[3];
    float4 A0 = av[0], A1 = av[1], A2 = av[2], A3 = av[3];
    float sd = d4(x0, x0) + d4(x1, x1) + d4(x2, x2) + d4(x3, x3);
    float exs = __expf(__ldg(beta) * sd);
    float r = 1.f / (g_den[i] + exs);
    float4 o0 = make_float4((A0.x + exs * h0.x) * r, (A0.y + exs * h0.y) * r,
                            (A0.z + exs * h0.z) * r, (A0.w + exs * h0.w) * r);
    float4 o1 = make_float4((A1.x + exs * h1.x) * r, (A1.y + exs * h1.y) * r,
                            (A1.z + exs * h1.z) * r, (A1.w + exs * h1.w) * r);
    float4 o2 = make_float4((A2.x + exs * h2.x) * r, (A2.y + exs * h2.y) * r,
                            (A2.z + exs * h2.z) * r, (A2.w + exs * h2.w) * r);
    float4 o3 = make_float4((A3.x + exs * h3.x) * r, (A3.y + exs * h3.y) * r,
                            (A3.z + exs * h3.z) * r, (A3.w + exs * h3.w) * r);
    float ss = d4(o0, o0) + d4(o1, o1) + d4(o2, o2) + d4(o3, o3);
    float inv = 1.f / fmaxf(sqrtf(ss), 1e-12f);
    float4* hb = (float4*)g_hB + o;
    hb[0] = o0; hb[1] = o1; hb[2] = o2; hb[3] = o3;
    float4* xb = (float4*)g_xnB + o;
    xb[0] = make_float4(o0.x * inv, o0.y * inv, o0.z * inv, o0.w * inv);
    xb[1] = make_float4(o1.x * inv, o1.y * inv, o1.z * inv, o1.w * inv);
    xb[2] = make_float4(o2.x * inv, o2.y * inv, o2.z * inv, o2.w * inv);
    xb[3] = make_float4(o3.x * inv, o3.y * inv, o3.z * inv, o3.w * inv);
    float4 z = make_float4(0.f, 0.f, 0.f, 0.f);
    av[0] = z; av[1] = z; av[2] = z; av[3] = z;
    g_den[i] = 0.f;
}

// ---------------------------------------------------------------------------
// Second conv finalize + folded lin2/gather dot + segment-sum into y[batch].
// ---------------------------------------------------------------------------
__global__ void final_kernel(const void* __restrict__ batchv,
                             const float* __restrict__ beta,
                             float* __restrict__ y, int n) {
    int i = blockIdx.x * blockDim.x + threadIdx.x;
    if (i >= n) return;
    size_t o = (size_t)i * 4;
    const float4* hv = (const float4*)g_hB + o;
    const float4* xv = (const float4*)g_xnB + o;
    const float4* av = (const float4*)g_acc + o;
    float4 h0 = hv[0], h1 = hv[1], h2 = hv[2], h3 = hv[3];
    float4 x0 = xv[0], x1 = xv[1], x2 = xv[2], x3 = xv[3];
    float4 A0 = av[0], A1 = av[1], A2 = av[2], A3 = av[3];
    float sd = d4(x0, x0) + d4(x1, x1) + d4(x2, x2) + d4(x3, x3);
    float exs = __expf(__ldg(beta) * sd);
    float r = 1.f / (g_den[i] + exs);
    float4 o0 = make_float4((A0.x + exs * h0.x) * r, (A0.y + exs * h0.y) * r,
                            (A0.z + exs * h0.z) * r, (A0.w + exs * h0.w) * r);
    float4 o1 = make_float4((A1.x + exs * h1.x) * r, (A1.y + exs * h1.y) * r,
                            (A1.z + exs * h1.z) * r, (A1.w + exs * h1.w) * r);
    float4 o2 = make_float4((A2.x + exs * h2.x) * r, (A2.y + exs * h2.y) * r,
                            (A2.z + exs * h2.z) * r, (A2.w + exs * h2.w) * r);
    float4 o3 = make_float4((A3.x + exs * h3.x) * r, (A3.y + exs * h3.y) * r,
                            (A3.z + exs * h3.z) * r, (A3.w + exs * h3.w) * r);
    const float4* vv = (const float4*)g_v;
    float s = d4(o0, vv[0]) + d4(o1, vv[1]) + d4(o2, vv[2]) + d4(o3, vv[3])
              + g_v[16];
    int b;
    if (g_idx64) b = (int)((const long long*)batchv)[i];
    else         b = ((const int*)batchv)[i];
    atomicAdd(y + b, s);
}

extern "C" void kernel_launch(void* const* d_in, const int* in_sizes, int n_in,
                              void* d_out, int out_size) {
    const float* x     = (const float*)d_in[0];
    const void*  ei    = d_in[1];
    const void*  batch = d_in[2];
    // num_graphs may or may not be materialized as an input; detect by size.
    int off = (in_sizes[3] == 16 * 75) ? 3 : 4;
    const float* lin1_w   = (const float*)d_in[off + 0];
    const float* lin1_b   = (const float*)d_in[off + 1];
    const float* beta1    = (const float*)d_in[off + 2];
    const float* beta2    = (const float*)d_in[off + 3];
    const float* lin2_w   = (const float*)d_in[off + 4];
    const float* lin2_b   = (const float*)d_in[off + 5];
    const float* gather_w = (const float*)d_in[off + 6];
    const float* gather_b = (const float*)d_in[off + 7];

    int n = in_sizes[0] / 75;
    long long E = (long long)in_sizes[1] / 2;
    int G = out_size;
    float* y = (float*)d_out;

    detect_kernel<<<1, 256>>>((const unsigned int*)ei);
    calc_v_kernel<<<1, 32>>>(lin2_w, lin2_b, gather_w);
    init_y_kernel<<<(G + 255) / 256, 256>>>(y, gather_b, G);
    lin1_kernel<<<(n + 127) / 128, 128>>>(x, lin1_w, lin1_b, n);

    long long ethreads = ((E + 7) / 8) * 32;
    int eblocks = (int)((ethreads + 255) / 256);
    edge_kernel<<<eblocks, 256>>>(ei, E, beta1, 0);
    finalize_kernel<<<(n + 255) / 256, 256>>>(beta1, n);
    edge_kernel<<<eblocks, 256>>>(ei, E, beta2, 1);
    final_kernel<<<(n + 255) / 256, 256>>>(batch, beta2, y, n);
}

// round 3
// speedup vs baseline: 1.0156x; 1.0156x over previous
#include <cuda_runtime.h>
#include <cuda_fp16.h>

#define NMAX 131072
#define EMAX 4194304
#define FD 16

__device__ float g_hA[NMAX * FD];
__device__ float g_hB[NMAX * FD];
__device__ __align__(16) __half g_xnhA[NMAX * FD];
__device__ __align__(16) __half g_xnhB[NMAX * FD];
__device__ float g_acc[NMAX * FD];
__device__ float g_den[NMAX];
__device__ int g_eidx[2 * EMAX];
__device__ __align__(16) float g_v[20];
__device__ int g_idx64;

__device__ __forceinline__ float d4(float4 a, float4 b) {
    return a.x * b.x + a.y * b.y + a.z * b.z + a.w * b.w;
}
__device__ __forceinline__ unsigned int packh2(float a, float b) {
    __half2 t = __floats2half2_rn(a, b);
    return *(unsigned int*)&t;
}

// ---------------------------------------------------------------------------
// int64 vs int32 index detection (odd 32-bit words all zero => int64).
// ---------------------------------------------------------------------------
__global__ void detect_kernel(const unsigned int* __restrict__ a) {
    __shared__ int any;
    if (threadIdx.x == 0) any = 0;
    __syncthreads();
    unsigned int v = a[2 * threadIdx.x + 1] | a[2 * (threadIdx.x + 256) + 1];
    if (v) atomicOr(&any, 1);
    __syncthreads();
    if (threadIdx.x == 0) g_idx64 = (any == 0) ? 1 : 0;
}

// ---------------------------------------------------------------------------
// Convert edge indices to int32 scratch (amortized over both edge passes).
// Each thread handles one pair of elements.
// ---------------------------------------------------------------------------
__global__ void convert_idx_kernel(const void* __restrict__ ei, long long m) {
    long long i = (long long)blockIdx.x * blockDim.x + threadIdx.x;
    long long idx = i * 2;
    if (idx >= m) return;
    if (g_idx64) {
        longlong2 v = __ldg((const longlong2*)ei + i);
        g_eidx[idx] = (int)v.x;
        g_eidx[idx + 1] = (int)v.y;
    } else {
        int2 v = __ldg((const int2*)ei + i);
        *(int2*)(g_eidx + idx) = v;
    }
}

// ---------------------------------------------------------------------------
// v[k] = sum_j gather_w[j] * lin2_w[j,k];  g_v[16] = gather_w . lin2_b
// ---------------------------------------------------------------------------
__global__ void calc_v_kernel(const float* __restrict__ lin2_w,
                              const float* __restrict__ lin2_b,
                              const float* __restrict__ gather_w) {
    int t = threadIdx.x;
    if (t < 16) {
        float s = 0.f;
        #pragma unroll
        for (int j = 0; j < 64; j++) s += gather_w[j] * lin2_w[j * 16 + t];
        g_v[t] = s;
    } else if (t == 16) {
        float s = 0.f;
        #pragma unroll
        for (int j = 0; j < 64; j++) s += gather_w[j] * lin2_b[j];
        g_v[16] = s;
    }
}

__global__ void init_y_kernel(float* __restrict__ y,
                              const float* __restrict__ gather_b, int g) {
    int i = blockIdx.x * blockDim.x + threadIdx.x;
    if (i < g) y[i] = gather_b[0];
}

// ---------------------------------------------------------------------------
// h = relu(x @ W1^T + b1); write h fp32, xn fp16; zero acc/den.
// 256 threads / 128 nodes: adjacent lane pairs split the k-range (split-k),
// combined via shfl_xor(1). Doubles occupancy vs 128-thread version.
// ---------------------------------------------------------------------------
__global__ void lin1_kernel(const float* __restrict__ x,
                            const float* __restrict__ w,
                            const float* __restrict__ b, int n) {
    __shared__ float sx[128 * 75];
    __shared__ float sw[75 * 16];
    __shared__ float sb[16];
    int tid = threadIdx.x;
    int bstart = blockIdx.x * 128;

    for (int i = tid; i < 75 * 16; i += 256) {
        int j = i / 75, k = i % 75;       // w is [16,75] row-major
        sw[k * 16 + j] = w[i];
    }
    if (tid < 16) sb[tid] = b[tid];

    int nodes = min(128, n - bstart);
    if (nodes == 128) {
        const float4* src = (const float4*)(x + (size_t)bstart * 75);
        float4* dst = (float4*)sx;
        #pragma unroll 4
        for (int i = tid; i < 128 * 75 / 4; i += 256) dst[i] = src[i];
    } else {
        for (int i = tid; i < nodes * 75; i += 256)
            sx[i] = x[(size_t)bstart * 75 + i];
    }
    __syncthreads();

    int node_l = tid >> 1;
    int half = tid & 1;
    int node_c = min(node_l, nodes - 1);  // clamp so shuffles stay uniform
    const float* row = sx + node_c * 75;
    const float4* swv = (const float4*)sw;

    float4 a0 = make_float4(0.f, 0.f, 0.f, 0.f);
    float4 a1 = a0, a2 = a0, a3 = a0;
    #pragma unroll 4
    for (int k = half; k < 75; k += 2) {
        float rk = row[k];
        float4 w0 = swv[k * 4 + 0];
        float4 w1 = swv[k * 4 + 1];
        float4 w2 = swv[k * 4 + 2];
        float4 w3 = swv[k * 4 + 3];
        a0.x += rk * w0.x; a0.y += rk * w0.y; a0.z += rk * w0.z; a0.w += rk * w0.w;
        a1.x += rk * w1.x; a1.y += rk * w1.y; a1.z += rk * w1.z; a1.w += rk * w1.w;
        a2.x += rk * w2.x; a2.y += rk * w2.y; a2.z += rk * w2.z; a2.w += rk * w2.w;
        a3.x += rk * w3.x; a3.y += rk * w3.y; a3.z += rk * w3.z; a3.w += rk * w3.w;
    }
    // combine split-k halves (lane pair)
    a0.x += __shfl_xor_sync(0xffffffffu, a0.x, 1);
    a0.y += __shfl_xor_sync(0xffffffffu, a0.y, 1);
    a0.z += __shfl_xor_sync(0xffffffffu, a0.z, 1);
    a0.w += __shfl_xor_sync(0xffffffffu, a0.w, 1);
    a1.x += __shfl_xor_sync(0xffffffffu, a1.x, 1);
    a1.y += __shfl_xor_sync(0xffffffffu, a1.y, 1);
    a1.z += __shfl_xor_sync(0xffffffffu, a1.z, 1);
    a1.w += __shfl_xor_sync(0xffffffffu, a1.w, 1);
    a2.x += __shfl_xor_sync(0xffffffffu, a2.x, 1);
    a2.y += __shfl_xor_sync(0xffffffffu, a2.y, 1);
    a2.z += __shfl_xor_sync(0xffffffffu, a2.z, 1);
    a2.w += __shfl_xor_sync(0xffffffffu, a2.w, 1);
    a3.x += __shfl_xor_sync(0xffffffffu, a3.x, 1);
    a3.y += __shfl_xor_sync(0xffffffffu, a3.y, 1);
    a3.z += __shfl_xor_sync(0xffffffffu, a3.z, 1);
    a3.w += __shfl_xor_sync(0xffffffffu, a3.w, 1);

    if (half || node_l >= nodes) return;
    int node = bstart + node_l;

    a0.x = fmaxf(a0.x + sb[0], 0.f);  a0.y = fmaxf(a0.y + sb[1], 0.f);
    a0.z = fmaxf(a0.z + sb[2], 0.f);  a0.w = fmaxf(a0.w + sb[3], 0.f);
    a1.x = fmaxf(a1.x + sb[4], 0.f);  a1.y = fmaxf(a1.y + sb[5], 0.f);
    a1.z = fmaxf(a1.z + sb[6], 0.f);  a1.w = fmaxf(a1.w + sb[7], 0.f);
    a2.x = fmaxf(a2.x + sb[8], 0.f);  a2.y = fmaxf(a2.y + sb[9], 0.f);
    a2.z = fmaxf(a2.z + sb[10], 0.f); a2.w = fmaxf(a2.w + sb[11], 0.f);
    a3.x = fmaxf(a3.x + sb[12], 0.f); a3.y = fmaxf(a3.y + sb[13], 0.f);
    a3.z = fmaxf(a3.z + sb[14], 0.f); a3.w = fmaxf(a3.w + sb[15], 0.f);

    float ss = d4(a0, a0) + d4(a1, a1) + d4(a2, a2) + d4(a3, a3);
    float inv = 1.f / fmaxf(sqrtf(ss), 1e-12f);

    size_t o = (size_t)node * 4;
    float4* hv = (float4*)g_hA + o;
    hv[0] = a0; hv[1] = a1; hv[2] = a2; hv[3] = a3;

    uint4 u0, u1;
    u0.x = packh2(a0.x * inv, a0.y * inv);
    u0.y = packh2(a0.z * inv, a0.w * inv);
    u0.z = packh2(a1.x * inv, a1.y * inv);
    u0.w = packh2(a1.z * inv, a1.w * inv);
    u1.x = packh2(a2.x * inv, a2.y * inv);
    u1.y = packh2(a2.z * inv, a2.w * inv);
    u1.z = packh2(a3.x * inv, a3.y * inv);
    u1.w = packh2(a3.z * inv, a3.w * inv);
    uint4* xp = (uint4*)(g_xnhA + (size_t)node * 16);
    xp[0] = u0; xp[1] = u1;

    float4 z = make_float4(0.f, 0.f, 0.f, 0.f);
    float4* av = (float4*)g_acc + o;
    av[0] = z; av[1] = z; av[2] = z; av[3] = z;
    g_den[node] = 0.f;
}

// ---------------------------------------------------------------------------
// Fused edge pass: acc[dst] += exp(beta * xn_s.xn_d) * h[src]; den[dst] += ex.
// 4 lanes per edge. xn gathered fp16 (1 L2 sector/node), h gathered fp32.
// ---------------------------------------------------------------------------
__global__ void edge_kernel(long long E, const float* __restrict__ beta,
                            int which) {
    const uint2* xn = (const uint2*)(which ? g_xnhB : g_xnhA);
    const float* h  = which ? g_hB : g_hA;
    const float b0 = __ldg(beta);
    int lane = threadIdx.x & 31;
    int c = lane & 3;
    long long warp = (((long long)blockIdx.x * blockDim.x) + threadIdx.x) >> 5;
    long long ebase = warp * 8;
    if (ebase >= E) return;
    long long e = ebase + (lane >> 2);
    bool ok = (e < E);
    int s = 0, d = 0;
    if (ok) {
        s = __ldg(g_eidx + e);
        d = __ldg(g_eidx + E + e);
    }
    float p = 0.f;
    if (ok) {
        uint2 us = __ldg(xn + s * 4 + c);
        uint2 ud = __ldg(xn + d * 4 + c);
        float2 s0 = __half22float2(*(const __half2*)&us.x);
        float2 s1 = __half22float2(*(const __half2*)&us.y);
        float2 d0 = __half22float2(*(const __half2*)&ud.x);
        float2 d1 = __half22float2(*(const __half2*)&ud.y);
        p = s0.x * d0.x + s0.y * d0.y + s1.x * d1.x + s1.y * d1.y;
    }
    p += __shfl_xor_sync(0xffffffffu, p, 1);
    p += __shfl_xor_sync(0xffffffffu, p, 2);
    if (!ok) return;
    float ex = __expf(b0 * p);
    float4 hs = __ldg((const float4*)h + (size_t)s * 4 + c);
    float* ap = g_acc + ((size_t)d * 16) + c * 4;
    asm volatile("red.global.add.v4.f32 [%0], {%1,%2,%3,%4};"
                 :: "l"(ap), "f"(ex * hs.x), "f"(ex * hs.y),
                    "f"(ex * hs.z), "f"(ex * hs.w)
                 : "memory");
    if (c == 0) atomicAdd(g_den + d, ex);
}

// ---------------------------------------------------------------------------
// Conv1 finalize: self-loop analytically (weight = exp(beta*[||h||>0])),
// divide by denom, renormalize into B buffers, re-zero acc/den.
// ---------------------------------------------------------------------------
__global__ void finalize_kernel(const float* __restrict__ beta, int n) {
    int i = blockIdx.x * blockDim.x + threadIdx.x;
    if (i >= n) return;
    size_t o = (size_t)i * 4;
    const float4* hv = (const float4*)g_hA + o;
    float4* av = (float4*)g_acc + o;
    float4 h0 = hv[0], h1 = hv[1], h2 = hv[2], h3 = hv[3];
    float4 A0 = av[0], A1 = av[1], A2 = av[2], A3 = av[3];
    float ssh = d4(h0, h0) + d4(h1, h1) + d4(h2, h2) + d4(h3, h3);
    float exs = __expf(__ldg(beta) * (ssh > 0.f ? 1.f : 0.f));
    float r = 1.f / (g_den[i] + exs);
    float4 o0 = make_float4((A0.x + exs * h0.x) * r, (A0.y + exs * h0.y) * r,
                            (A0.z + exs * h0.z) * r, (A0.w + exs * h0.w) * r);
    float4 o1 = make_float4((A1.x + exs * h1.x) * r, (A1.y + exs * h1.y) * r,
                            (A1.z + exs * h1.z) * r, (A1.w + exs * h1.w) * r);
    float4 o2 = make_float4((A2.x + exs * h2.x) * r, (A2.y + exs * h2.y) * r,
                            (A2.z + exs * h2.z) * r, (A2.w + exs * h2.w) * r);
    float4 o3 = make_float4((A3.x + exs * h3.x) * r, (A3.y + exs * h3.y) * r,
                            (A3.z + exs * h3.z) * r, (A3.w + exs * h3.w) * r);
    float ss = d4(o0, o0) + d4(o1, o1) + d4(o2, o2) + d4(o3, o3);
    float inv = 1.f / fmaxf(sqrtf(ss), 1e-12f);
    float4* hb = (float4*)g_hB + o;
    hb[0] = o0; hb[1] = o1; hb[2] = o2; hb[3] = o3;
    uint4 u0, u1;
    u0.x = packh2(o0.x * inv, o0.y * inv);
    u0.y = packh2(o0.z * inv, o0.w * inv);
    u0.z = packh2(o1.x * inv, o1.y * inv);
    u0.w = packh2(o1.z * inv, o1.w * inv);
    u1.x = packh2(o2.x * inv, o2.y * inv);
    u1.y = packh2(o2.z * inv, o2.w * inv);
    u1.z = packh2(o3.x * inv, o3.y * inv);
    u1.w = packh2(o3.z * inv, o3.w * inv);
    uint4* xp = (uint4*)(g_xnhB + (size_t)i * 16);
    xp[0] = u0; xp[1] = u1;
    float4 z = make_float4(0.f, 0.f, 0.f, 0.f);
    av[0] = z; av[1] = z; av[2] = z; av[3] = z;
    g_den[i] = 0.f;
}

// ---------------------------------------------------------------------------
// Conv2 finalize + folded lin2/gather dot + segment-sum into y[batch].
// ---------------------------------------------------------------------------
__global__ void final_kernel(const void* __restrict__ batchv,
                             const float* __restrict__ beta,
                             float* __restrict__ y, int n) {
    int i = blockIdx.x * blockDim.x + threadIdx.x;
    if (i >= n) return;
    size_t o = (size_t)i * 4;
    const float4* hv = (const float4*)g_hB + o;
    const float4* av = (const float4*)g_acc + o;
    float4 h0 = hv[0], h1 = hv[1], h2 = hv[2], h3 = hv[3];
    float4 A0 = av[0], A1 = av[1], A2 = av[2], A3 = av[3];
    float ssh = d4(h0, h0) + d4(h1, h1) + d4(h2, h2) + d4(h3, h3);
    float exs = __expf(__ldg(beta) * (ssh > 0.f ? 1.f : 0.f));
    float r = 1.f / (g_den[i] + exs);
    float4 o0 = make_float4((A0.x + exs * h0.x) * r, (A0.y + exs * h0.y) * r,
                            (A0.z + exs * h0.z) * r, (A0.w + exs * h0.w) * r);
    float4 o1 = make_float4((A1.x + exs * h1.x) * r, (A1.y + exs * h1.y) * r,
                            (A1.z + exs * h1.z) * r, (A1.w + exs * h1.w) * r);
    float4 o2 = make_float4((A2.x + exs * h2.x) * r, (A2.y + exs * h2.y) * r,
                            (A2.z + exs * h2.z) * r, (A2.w + exs * h2.w) * r);
    float4 o3 = make_float4((A3.x + exs * h3.x) * r, (A3.y + exs * h3.y) * r,
                            (A3.z + exs * h3.z) * r, (A3.w + exs * h3.w) * r);
    const float4* vv = (const float4*)g_v;
    float s = d4(o0, vv[0]) + d4(o1, vv[1]) + d4(o2, vv[2]) + d4(o3, vv[3])
              + g_v[16];
    int b;
    if (g_idx64) b = (int)((const long long*)batchv)[i];
    else         b = ((const int*)batchv)[i];
    atomicAdd(y + b, s);
}

extern "C" void kernel_launch(void* const* d_in, const int* in_sizes, int n_in,
                              void* d_out, int out_size) {
    const float* x     = (const float*)d_in[0];
    const void*  ei    = d_in[1];
    const void*  batch = d_in[2];
    int off = (in_sizes[3] == 16 * 75) ? 3 : 4;
    const float* lin1_w   = (const float*)d_in[off + 0];
    const float* lin1_b   = (const float*)d_in[off + 1];
    const float* beta1    = (const float*)d_in[off + 2];
    const float* beta2    = (const float*)d_in[off + 3];
    const float* lin2_w   = (const float*)d_in[off + 4];
    const float* lin2_b   = (const float*)d_in[off + 5];
    const float* gather_w = (const float*)d_in[off + 6];
    const float* gather_b = (const float*)d_in[off + 7];

    int n = in_sizes[0] / 75;
    long long E = (long long)in_sizes[1] / 2;
    int G = out_size;
    float* y = (float*)d_out;

    detect_kernel<<<1, 256>>>((const unsigned int*)ei);
    long long pairs = E;  // convert handles 2 elements each over 2E
    convert_idx_kernel<<<(int)((pairs + 255) / 256), 256>>>(ei, 2 * E);
    calc_v_kernel<<<1, 32>>>(lin2_w, lin2_b, gather_w);
    init_y_kernel<<<(G + 255) / 256, 256>>>(y, gather_b, G);
    lin1_kernel<<<(n + 127) / 128, 256>>>(x, lin1_w, lin1_b, n);

    long long ethreads = ((E + 7) / 8) * 32;
    int eblocks = (int)((ethreads + 255) / 256);
    edge_kernel<<<eblocks, 256>>>(E, beta1, 0);
    finalize_kernel<<<(n + 255) / 256, 256>>>(beta1, n);
    edge_kernel<<<eblocks, 256>>>(E, beta2, 1);
    final_kernel<<<(n + 255) / 256, 256>>>(batch, beta2, y, n);
}